// round 9
// baseline (speedup 1.0000x reference)
#include <cuda_runtime.h>

#define N_NODES 50000
#define N_EDGES 800000
#define ET (N_EDGES + N_NODES)   // self-loops appended
#define N_GRAPHS 64
#define FULL 0xffffffffu
#define NB_SCAN ((N_NODES + 255) / 256)   // 196

// ---------------- scratch (device globals; zero at module load) ------------
__device__ __align__(16) float g_xl1[N_NODES * 128];
__device__ __align__(16) float g_xr1[N_NODES * 128];
__device__ __align__(16) float g_xl2[N_NODES * 4];
__device__ __align__(16) float g_xr2[N_NODES * 4];
__device__ int g_cnt[N_NODES];          // invariant: zero at kernel_launch entry
__device__ int g_rowptr[N_NODES + 1];
__device__ int g_cursor[N_NODES];
__device__ int g_csr_src[ET];
__device__ int g_bsum[NB_SCAN];
__device__ float g_pool[N_GRAPHS * 4];  // invariant: zero at kernel_launch entry

__device__ __forceinline__ float lrelu(float v) { return v > 0.f ? v : 0.2f * v; }

// f32x2 packed FMA (sm_100+): d = a*b + d, elementwise on packed pairs
#define FMA2(d, a, b) asm("fma.rn.f32x2 %0, %1, %2, %0;" : "+l"(d) : "l"(a), "l"(b))
__device__ __forceinline__ unsigned long long pack2(float lo, float hi) {
    unsigned long long r;
    asm("mov.b64 %0, {%1, %2};" : "=l"(r) : "f"(lo), "f"(hi));
    return r;
}
__device__ __forceinline__ void unpack2(unsigned long long v, float& lo, float& hi) {
    asm("mov.b64 {%0, %1}, %2;" : "=f"(lo), "=f"(hi) : "l"(v));
}

// ---------------- CSR: count incoming edges per dst -------------------------
__global__ void csr_count_kernel(const int* __restrict__ ei) {
    int e = blockIdx.x * blockDim.x + threadIdx.x;
    if (e < ET) {
        int dst = (e < N_EDGES) ? ei[N_EDGES + e] : (e - N_EDGES);
        atomicAdd(&g_cnt[dst], 1);
    }
}

// ---------------- scan phase 1: per-block exclusive scan --------------------
__global__ void scan_local_kernel() {
    __shared__ int sh[256];
    int t = threadIdx.x;
    int i = blockIdx.x * 256 + t;
    int v = (i < N_NODES) ? g_cnt[i] : 0;
    sh[t] = v;
    __syncthreads();
#pragma unroll
    for (int off = 1; off < 256; off <<= 1) {
        int u = (t >= off) ? sh[t - off] : 0;
        __syncthreads();
        sh[t] += u;
        __syncthreads();
    }
    if (i < N_NODES) g_rowptr[i] = sh[t] - v;          // exclusive within block
    if (t == 255) g_bsum[blockIdx.x] = sh[255];        // block total
}

// ---------------- scan phase 2: apply (each block sums its own prefix) ------
__global__ void scan_apply_kernel() {
    __shared__ int sh[256];
    int t = threadIdx.x, bid = blockIdx.x;
    sh[t] = (t < bid) ? g_bsum[t] : 0;   // NB_SCAN = 196 <= 256
    __syncthreads();
#pragma unroll
    for (int off = 128; off; off >>= 1) {
        if (t < off) sh[t] += sh[t + off];
        __syncthreads();
    }
    int boff = sh[0];
    int i = bid * 256 + t;
    if (i < N_NODES) {
        int r = g_rowptr[i] + boff;
        g_rowptr[i] = r;
        g_cursor[i] = r;
    }
    if (i == 0) g_rowptr[N_NODES] = ET;
}

// ---------------- CSR: scatter src ids into slots --------------------------
__global__ void csr_fill_kernel(const int* __restrict__ ei) {
    int e = blockIdx.x * blockDim.x + threadIdx.x;
    if (e >= ET) return;
    int src, dst;
    if (e < N_EDGES) { src = ei[e]; dst = ei[N_EDGES + e]; }
    else             { src = dst = e - N_EDGES; }
    int pos = atomicAdd(&g_cursor[dst], 1);
    g_csr_src[pos] = src;
}

// ---------------- restore g_cnt invariant (runs under fused_l1's shadow) ---
__global__ void zero_cnt_kernel() {
    int i = blockIdx.x * blockDim.x + threadIdx.x;
    if (i < N_NODES) g_cnt[i] = 0;
}

// ---------------- GEMM1 (known good): 32-row tile, f32x2 FMA ---------------
__global__ void gemm1_kernel(const float* __restrict__ x,
                             const float* __restrict__ Wl,
                             const float* __restrict__ Wr) {
    __shared__ float xs[32][128];
    int row0 = blockIdx.x * 32;
    float4* xsv = (float4*)&xs[0][0];
    for (int i = threadIdx.x; i < 32 * 32; i += 256) {
        int r = row0 + (i >> 5);
        float4 v = make_float4(0.f, 0.f, 0.f, 0.f);
        if (r < N_NODES) v = ((const float4*)x)[(size_t)r * 32 + (i & 31)];
        xsv[i] = v;
    }
    __syncthreads();

    int tx = threadIdx.x & 63;
    int ty = threadIdx.x >> 6;

    unsigned long long acc[4][4];
#pragma unroll
    for (int c = 0; c < 4; c++)
#pragma unroll
        for (int p = 0; p < 4; p++) acc[c][p] = 0ull;

#pragma unroll 2
    for (int k = 0; k < 128; k++) {
        unsigned long long wp[4];
        wp[0] = pack2(Wl[k * 128 + tx],      Wl[k * 128 + tx]);
        wp[1] = pack2(Wl[k * 128 + tx + 64], Wl[k * 128 + tx + 64]);
        wp[2] = pack2(Wr[k * 128 + tx],      Wr[k * 128 + tx]);
        wp[3] = pack2(Wr[k * 128 + tx + 64], Wr[k * 128 + tx + 64]);
#pragma unroll
        for (int p = 0; p < 4; p++) {
            unsigned long long xp = pack2(xs[ty * 8 + 2 * p][k], xs[ty * 8 + 2 * p + 1][k]);
#pragma unroll
            for (int c = 0; c < 4; c++) FMA2(acc[c][p], xp, wp[c]);
        }
    }

#pragma unroll
    for (int p = 0; p < 4; p++) {
#pragma unroll
        for (int c = 0; c < 4; c++) {
            float lo, hi;
            unpack2(acc[c][p], lo, hi);
            int r_lo = row0 + ty * 8 + 2 * p;
            int col = (c & 1) ? tx + 64 : tx;
            float* dstbuf = (c < 2) ? g_xl1 : g_xr1;
            if (r_lo < N_NODES)     dstbuf[(size_t)r_lo * 128 + col] = lo;
            if (r_lo + 1 < N_NODES) dstbuf[(size_t)(r_lo + 1) * 128 + col] = hi;
        }
    }
}

// ---------------- fused layer1 + bias + ELU + GEMM2: warp per dst ----------
// lanes 0-15 head0 (ch 0..63), 16-31 head1. 8 edges in flight per warp.
__global__ void fused_l1_kernel(const float* __restrict__ att1,
                                const float* __restrict__ b1,
                                const float* __restrict__ W2l,
                                const float* __restrict__ W2r) {
    int dst = (blockIdx.x * blockDim.x + threadIdx.x) >> 5;
    if (dst >= N_NODES) return;
    int lane = threadIdx.x & 31;
    int c0 = lane * 4;

    float4 b  = *(const float4*)(g_xr1 + (size_t)dst * 128 + c0);
    float4 at = *(const float4*)(att1 + c0);

    float4 acc = make_float4(0.f, 0.f, 0.f, 0.f);
    float denom = 0.f;

    int rs = g_rowptr[dst], re = g_rowptr[dst + 1];
    for (int i0 = rs; i0 < re; i0 += 32) {
        int n = re - i0; if (n > 32) n = 32;
        int sidx = (i0 + lane < re) ? g_csr_src[i0 + lane] : 0;
        int j = 0;
        for (; j + 8 <= n; j += 8) {
            float4 A[8];
            float  P[8];
#pragma unroll
            for (int u = 0; u < 8; u++) {
                int s = __shfl_sync(FULL, sidx, j + u);
                A[u] = *(const float4*)(g_xl1 + (size_t)s * 128 + c0);
            }
#pragma unroll
            for (int u = 0; u < 8; u++)
                P[u] = at.x * lrelu(A[u].x + b.x) + at.y * lrelu(A[u].y + b.y)
                     + at.z * lrelu(A[u].z + b.z) + at.w * lrelu(A[u].w + b.w);
#pragma unroll
            for (int s = 8; s; s >>= 1) {   // 16-lane groups => per-head sums
#pragma unroll
                for (int u = 0; u < 8; u++) P[u] += __shfl_xor_sync(FULL, P[u], s);
            }
#pragma unroll
            for (int u = 0; u < 8; u++) {
                float e = __expf(P[u]);
                denom += e;
                acc.x += e * A[u].x; acc.y += e * A[u].y;
                acc.z += e * A[u].z; acc.w += e * A[u].w;
            }
        }
        for (; j + 4 <= n; j += 4) {
            float4 A[4];
            float  P[4];
#pragma unroll
            for (int u = 0; u < 4; u++) {
                int s = __shfl_sync(FULL, sidx, j + u);
                A[u] = *(const float4*)(g_xl1 + (size_t)s * 128 + c0);
            }
#pragma unroll
            for (int u = 0; u < 4; u++)
                P[u] = at.x * lrelu(A[u].x + b.x) + at.y * lrelu(A[u].y + b.y)
                     + at.z * lrelu(A[u].z + b.z) + at.w * lrelu(A[u].w + b.w);
#pragma unroll
            for (int s = 8; s; s >>= 1) {
#pragma unroll
                for (int u = 0; u < 4; u++) P[u] += __shfl_xor_sync(FULL, P[u], s);
            }
#pragma unroll
            for (int u = 0; u < 4; u++) {
                float e = __expf(P[u]);
                denom += e;
                acc.x += e * A[u].x; acc.y += e * A[u].y;
                acc.z += e * A[u].z; acc.w += e * A[u].w;
            }
        }
        for (; j < n; j++) {
            int src = __shfl_sync(FULL, sidx, j);
            float4 a = *(const float4*)(g_xl1 + (size_t)src * 128 + c0);
            float p = at.x * lrelu(a.x + b.x) + at.y * lrelu(a.y + b.y)
                    + at.z * lrelu(a.z + b.z) + at.w * lrelu(a.w + b.w);
#pragma unroll
            for (int s = 8; s; s >>= 1) p += __shfl_xor_sync(FULL, p, s);
            float ea = __expf(p);
            denom += ea;
            acc.x += ea * a.x; acc.y += ea * a.y;
            acc.z += ea * a.z; acc.w += ea * a.w;
        }
    }

    float w = __fdividef(1.f, denom + 1e-16f);
    float4 bias = *(const float4*)(b1 + c0);
    float ov[4];
    ov[0] = acc.x * w + bias.x;
    ov[1] = acc.y * w + bias.y;
    ov[2] = acc.z * w + bias.z;
    ov[3] = acc.w * w + bias.w;
#pragma unroll
    for (int j = 0; j < 4; j++)
        ov[j] = ov[j] > 0.f ? ov[j] : (__expf(ov[j]) - 1.f);   // ELU

    // fused GEMM2: pl[c] = sum_k ov[k] * W2l[k][c] (k = c0..c0+3 per lane)
    float pl0 = 0.f, pl1 = 0.f, pl2 = 0.f, pr0 = 0.f, pr1 = 0.f, pr2 = 0.f;
#pragma unroll
    for (int j = 0; j < 4; j++) {
        int k = c0 + j;
        pl0 += ov[j] * W2l[k * 3 + 0];
        pl1 += ov[j] * W2l[k * 3 + 1];
        pl2 += ov[j] * W2l[k * 3 + 2];
        pr0 += ov[j] * W2r[k * 3 + 0];
        pr1 += ov[j] * W2r[k * 3 + 1];
        pr2 += ov[j] * W2r[k * 3 + 2];
    }
#pragma unroll
    for (int s = 16; s; s >>= 1) {
        pl0 += __shfl_xor_sync(FULL, pl0, s);
        pl1 += __shfl_xor_sync(FULL, pl1, s);
        pl2 += __shfl_xor_sync(FULL, pl2, s);
        pr0 += __shfl_xor_sync(FULL, pr0, s);
        pr1 += __shfl_xor_sync(FULL, pr1, s);
        pr2 += __shfl_xor_sync(FULL, pr2, s);
    }
    if (lane == 0) {
        *(float4*)(g_xl2 + dst * 4) = make_float4(pl0, pl1, pl2, 0.f);
        *(float4*)(g_xr2 + dst * 4) = make_float4(pr0, pr1, pr2, 0.f);
    }
}

// ---------------- fused layer 2 + pool scatter: warp per dst ----------------
__global__ void fused_l2_kernel(const float* __restrict__ att2,
                                const float* __restrict__ b2,
                                const int* __restrict__ batch) {
    int dst = (blockIdx.x * blockDim.x + threadIdx.x) >> 5;
    if (dst >= N_NODES) return;
    int lane = threadIdx.x & 31;
    float a0 = att2[0], a1 = att2[1], a2 = att2[2];
    float4 rv = *(const float4*)(g_xr2 + dst * 4);
    float d = 0.f, m0 = 0.f, m1 = 0.f, m2 = 0.f;
    int rs = g_rowptr[dst], re = g_rowptr[dst + 1];
    for (int i = rs + lane; i < re; i += 32) {
        int src = g_csr_src[i];
        float4 sv = *(const float4*)(g_xl2 + src * 4);
        float p = a0 * lrelu(sv.x + rv.x) + a1 * lrelu(sv.y + rv.y) + a2 * lrelu(sv.z + rv.z);
        float ea = __expf(p);
        d += ea; m0 += ea * sv.x; m1 += ea * sv.y; m2 += ea * sv.z;
    }
#pragma unroll
    for (int o = 16; o; o >>= 1) {
        d  += __shfl_xor_sync(FULL, d, o);
        m0 += __shfl_xor_sync(FULL, m0, o);
        m1 += __shfl_xor_sync(FULL, m1, o);
        m2 += __shfl_xor_sync(FULL, m2, o);
    }
    if (lane == 0) {
        float w = __fdividef(1.f, d + 1e-16f);
        int g = batch[dst];
        atomicAdd(&g_pool[g * 4 + 0], m0 * w + b2[0]);
        atomicAdd(&g_pool[g * 4 + 1], m1 * w + b2[1]);
        atomicAdd(&g_pool[g * 4 + 2], m2 * w + b2[2]);
    }
}

// ---------------- final MLP + pool-count via sorted-batch binary search -----
__global__ void mlp_kernel(const int* __restrict__ batch,
                           const float* __restrict__ Wr1, const float* __restrict__ br1,
                           const float* __restrict__ Wr2, const float* __restrict__ br2,
                           float* __restrict__ out) {
    int g = threadIdx.x;
    float o0 = 0.f, o1 = 0.f, o2 = 0.f;
    float v0 = 0.f, v1 = 0.f, v2 = 0.f;
    if (g < N_GRAPHS) {
        // cnt = lower_bound(batch, g+1) - lower_bound(batch, g)   (batch sorted)
        int lo0 = 0, hi0 = N_NODES;
        while (lo0 < hi0) { int m = (lo0 + hi0) >> 1; if (batch[m] < g) lo0 = m + 1; else hi0 = m; }
        int lo1 = 0, hi1 = N_NODES;
        while (lo1 < hi1) { int m = (lo1 + hi1) >> 1; if (batch[m] < g + 1) lo1 = m + 1; else hi1 = m; }
        float cnt = (float)(lo1 - lo0);
        float inv = 1.f / fmaxf(cnt, 1.f);
        v0 = g_pool[g * 4 + 0] * inv;
        v1 = g_pool[g * 4 + 1] * inv;
        v2 = g_pool[g * 4 + 2] * inv;
        o0 = br2[0]; o1 = br2[1]; o2 = br2[2];
#pragma unroll 8
        for (int j = 0; j < 64; j++) {
            float hj = v0 * Wr1[j] + v1 * Wr1[64 + j] + v2 * Wr1[128 + j] + br1[j];
            hj = fmaxf(hj, 0.f);
            o0 += hj * Wr2[j * 3 + 0];
            o1 += hj * Wr2[j * 3 + 1];
            o2 += hj * Wr2[j * 3 + 2];
        }
        out[g * 3 + 0] = o0;
        out[g * 3 + 1] = o1;
        out[g * 3 + 2] = o2;
    }
    __syncthreads();
    // restore g_pool invariant for next replay (256 floats, 64 threads)
#pragma unroll
    for (int q = 0; q < 4; q++) g_pool[q * 64 + threadIdx.x] = 0.f;
}

// ---------------- stream/event handles (created at static init) -------------
struct SideStream {
    cudaStream_t s;
    cudaEvent_t evFork, evGemm, evFill, evSide;
    SideStream() {
        cudaStreamCreateWithFlags(&s, cudaStreamNonBlocking);
        cudaEventCreateWithFlags(&evFork, cudaEventDisableTiming);
        cudaEventCreateWithFlags(&evGemm, cudaEventDisableTiming);
        cudaEventCreateWithFlags(&evFill, cudaEventDisableTiming);
        cudaEventCreateWithFlags(&evSide, cudaEventDisableTiming);
    }
};
static SideStream g_ss;

// ---------------- launch ----------------------------------------------------
extern "C" void kernel_launch(void* const* d_in, const int* in_sizes, int n_in,
                              void* d_out, int out_size) {
    (void)in_sizes; (void)n_in; (void)out_size;
    const float* x    = (const float*)d_in[0];
    const int*   ei   = (const int*)  d_in[1];
    const int*   batch= (const int*)  d_in[2];
    const float* W1l  = (const float*)d_in[3];
    const float* W1r  = (const float*)d_in[4];
    const float* att1 = (const float*)d_in[5];
    const float* b1   = (const float*)d_in[6];
    const float* W2l  = (const float*)d_in[7];
    const float* W2r  = (const float*)d_in[8];
    const float* att2 = (const float*)d_in[9];
    const float* b2   = (const float*)d_in[10];
    const float* Wr1  = (const float*)d_in[11];
    const float* br1  = (const float*)d_in[12];
    const float* Wr2  = (const float*)d_in[13];
    const float* br2  = (const float*)d_in[14];
    float* out = (float*)d_out;

    // fork: gemm1 runs concurrently with the CSR build
    cudaEventRecord(g_ss.evFork, 0);
    cudaStreamWaitEvent(g_ss.s, g_ss.evFork, 0);
    gemm1_kernel<<<(N_NODES + 31) / 32, 256, 0, g_ss.s>>>(x, W1l, W1r);
    cudaEventRecord(g_ss.evGemm, g_ss.s);

    csr_count_kernel<<<(ET + 255) / 256, 256>>>(ei);
    scan_local_kernel<<<NB_SCAN, 256>>>();
    scan_apply_kernel<<<NB_SCAN, 256>>>();
    csr_fill_kernel<<<(ET + 255) / 256, 256>>>(ei);

    // g_cnt is dead after fill: restore its zero-invariant on the side stream,
    // overlapped with fused_l1.
    cudaEventRecord(g_ss.evFill, 0);
    cudaStreamWaitEvent(g_ss.s, g_ss.evFill, 0);
    zero_cnt_kernel<<<(N_NODES + 255) / 256, 256, 0, g_ss.s>>>();
    cudaEventRecord(g_ss.evSide, g_ss.s);

    // join gemm1 before fused_l1
    cudaStreamWaitEvent(0, g_ss.evGemm, 0);
    {
        long long t = (long long)N_NODES * 32;
        fused_l1_kernel<<<(unsigned)((t + 255) / 256), 256>>>(att1, b1, W2l, W2r);
        fused_l2_kernel<<<(unsigned)((t + 255) / 256), 256>>>(att2, b2, batch);
    }
    // join side stream before the final kernel so the graph is fully joined
    cudaStreamWaitEvent(0, g_ss.evSide, 0);
    mlp_kernel<<<1, 64>>>(batch, Wr1, br1, Wr2, br2, out);
}

// round 10
// speedup vs baseline: 1.1986x; 1.1986x over previous
#include <cuda_runtime.h>

#define N_NODES 50000
#define N_EDGES 800000
#define ET (N_EDGES + N_NODES)   // self-loops appended
#define N_GRAPHS 64
#define FULL 0xffffffffu
#define NB_SCAN ((N_NODES + 255) / 256)   // 196

// ---------------- scratch (device globals; no allocations) ----------------
__device__ __align__(16) float g_xl1[N_NODES * 128];
__device__ __align__(16) float g_xr1[N_NODES * 128];
__device__ __align__(16) float g_xl2[N_NODES * 4];
__device__ __align__(16) float g_xr2[N_NODES * 4];
__device__ int g_cnt[N_NODES];
__device__ int g_rowptr[N_NODES + 1];
__device__ int g_cursor[N_NODES];
__device__ int g_csr_src[ET];
__device__ int g_bsum[NB_SCAN];
__device__ float g_pool[N_GRAPHS * 4];

__device__ __forceinline__ float lrelu(float v) { return v > 0.f ? v : 0.2f * v; }

// f32x2 packed FMA (sm_100+): d = a*b + d, elementwise on packed pairs
#define FMA2(d, a, b) asm("fma.rn.f32x2 %0, %1, %2, %0;" : "+l"(d) : "l"(a), "l"(b))
__device__ __forceinline__ unsigned long long pack2(float lo, float hi) {
    unsigned long long r;
    asm("mov.b64 %0, {%1, %2};" : "=l"(r) : "f"(lo), "f"(hi));
    return r;
}
__device__ __forceinline__ void unpack2(unsigned long long v, float& lo, float& hi) {
    asm("mov.b64 {%0, %1}, %2;" : "=f"(lo), "=f"(hi) : "l"(v));
}

// ---------------- init ------------------------------------------------------
__global__ void init_kernel() {
    int i = blockIdx.x * blockDim.x + threadIdx.x;
    if (i < N_NODES) g_cnt[i] = 0;
    if (i < N_GRAPHS * 4) g_pool[i] = 0.f;
}

// ---------------- CSR: count incoming edges per dst (+ per-graph node cnt) -
__global__ void csr_count_kernel(const int* __restrict__ ei,
                                 const int* __restrict__ batch) {
    int e = blockIdx.x * blockDim.x + threadIdx.x;
    if (e < ET) {
        int dst = (e < N_EDGES) ? ei[N_EDGES + e] : (e - N_EDGES);
        atomicAdd(&g_cnt[dst], 1);
    }
    if (e < N_NODES) atomicAdd(&g_pool[batch[e] * 4 + 3], 1.f);
}

// ---------------- scan phase 1: per-block exclusive scan --------------------
__global__ void scan_local_kernel() {
    __shared__ int sh[256];
    int t = threadIdx.x;
    int i = blockIdx.x * 256 + t;
    int v = (i < N_NODES) ? g_cnt[i] : 0;
    sh[t] = v;
    __syncthreads();
#pragma unroll
    for (int off = 1; off < 256; off <<= 1) {
        int u = (t >= off) ? sh[t - off] : 0;
        __syncthreads();
        sh[t] += u;
        __syncthreads();
    }
    if (i < N_NODES) g_rowptr[i] = sh[t] - v;          // exclusive within block
    if (t == 255) g_bsum[blockIdx.x] = sh[255];        // block total
}

// ---------------- scan phase 2: apply (each block sums its own prefix) ------
__global__ void scan_apply_kernel() {
    __shared__ int sh[256];
    int t = threadIdx.x, bid = blockIdx.x;
    sh[t] = (t < bid) ? g_bsum[t] : 0;   // NB_SCAN = 196 <= 256
    __syncthreads();
#pragma unroll
    for (int off = 128; off; off >>= 1) {
        if (t < off) sh[t] += sh[t + off];
        __syncthreads();
    }
    int boff = sh[0];
    int i = bid * 256 + t;
    if (i < N_NODES) {
        int r = g_rowptr[i] + boff;
        g_rowptr[i] = r;
        g_cursor[i] = r;
    }
    if (i == 0) g_rowptr[N_NODES] = ET;
}

// ---------------- CSR: scatter src ids into slots --------------------------
__global__ void csr_fill_kernel(const int* __restrict__ ei) {
    int e = blockIdx.x * blockDim.x + threadIdx.x;
    if (e >= ET) return;
    int src, dst;
    if (e < N_EDGES) { src = ei[e]; dst = ei[N_EDGES + e]; }
    else             { src = dst = e - N_EDGES; }
    int pos = atomicAdd(&g_cursor[dst], 1);
    g_csr_src[pos] = src;
}

// ---------------- GEMM1 v3: 128x128 tile, K-chunked smem, reg-tiled --------
// grid (391, 2): y=0 -> Wl -> g_xl1, y=1 -> Wr -> g_xr1.
// thread: 4 rows (rg*4..) x 16 cols (cg*4 + s*32, s=0..3). Per k:
// 1 LDS.128 a-frag + 4 LDS.128 b-frag + 32 FMA2  -> FMA-bound.
#define G3_KC 32
#define G3_PAD 132
__global__ void __launch_bounds__(256, 2)
gemm1_kernel(const float* __restrict__ x,
             const float* __restrict__ Wl,
             const float* __restrict__ Wr) {
    __shared__ float xs[G3_KC][G3_PAD];   // [k][row], 16B-aligned padded stride
    __shared__ float ws[G3_KC][G3_PAD];   // [k][col]
    int row0 = blockIdx.x * 128;
    const float* W = blockIdx.y ? Wr : Wl;
    int tid = threadIdx.x;
    int rg = tid >> 3;    // 0..31: rows rg*4 .. rg*4+3
    int cg = tid & 7;     // 0..7 : cols cg*4 + 32s + {0..3}

    unsigned long long acc[4][8];
#pragma unroll
    for (int r = 0; r < 4; r++)
#pragma unroll
        for (int c = 0; c < 8; c++) acc[r][c] = 0ull;

    for (int k0 = 0; k0 < 128; k0 += G3_KC) {
        // stage x transposed: thread -> row tid>>1, k-half (tid&1)*16
        {
            int r = tid >> 1;
            int kb = (tid & 1) * 16;
            int grow = row0 + r;
#pragma unroll
            for (int j4 = 0; j4 < 4; j4++) {
                float4 v = make_float4(0.f, 0.f, 0.f, 0.f);
                if (grow < N_NODES)
                    v = *(const float4*)(x + (size_t)grow * 128 + k0 + kb + j4 * 4);
                xs[kb + j4 * 4 + 0][r] = v.x;
                xs[kb + j4 * 4 + 1][r] = v.y;
                xs[kb + j4 * 4 + 2][r] = v.z;
                xs[kb + j4 * 4 + 3][r] = v.w;
            }
        }
        // stage W: thread -> k-row tid>>3, col segment (tid&7)*16
        {
            int k = tid >> 3;
            int cs = (tid & 7) * 16;
#pragma unroll
            for (int j4 = 0; j4 < 4; j4++) {
                float4 v = *(const float4*)(W + (size_t)(k0 + k) * 128 + cs + j4 * 4);
                *(float4*)&ws[k][cs + j4 * 4] = v;
            }
        }
        __syncthreads();
#pragma unroll 4
        for (int k = 0; k < G3_KC; k++) {
            float4 av = *(const float4*)&xs[k][rg * 4];
            unsigned long long ap[4];
            ap[0] = pack2(av.x, av.x);
            ap[1] = pack2(av.y, av.y);
            ap[2] = pack2(av.z, av.z);
            ap[3] = pack2(av.w, av.w);
#pragma unroll
            for (int s = 0; s < 4; s++) {
                float4 bv = *(const float4*)&ws[k][cg * 4 + s * 32];
                unsigned long long b0 = pack2(bv.x, bv.y);
                unsigned long long b1 = pack2(bv.z, bv.w);
#pragma unroll
                for (int r = 0; r < 4; r++) {
                    FMA2(acc[r][2 * s + 0], ap[r], b0);
                    FMA2(acc[r][2 * s + 1], ap[r], b1);
                }
            }
        }
        __syncthreads();
    }

    float* outbuf = blockIdx.y ? g_xr1 : g_xl1;
#pragma unroll
    for (int r = 0; r < 4; r++) {
        int grow = row0 + rg * 4 + r;
        if (grow >= N_NODES) continue;
#pragma unroll
        for (int s = 0; s < 4; s++) {
            float4 o;
            unpack2(acc[r][2 * s + 0], o.x, o.y);
            unpack2(acc[r][2 * s + 1], o.z, o.w);
            *(float4*)(outbuf + (size_t)grow * 128 + cg * 4 + s * 32) = o;
        }
    }
}

// ---------------- fused layer1 + bias + ELU + GEMM2: warp per dst ----------
// lanes 0-15 head0 (ch 0..63), 16-31 head1. 8 edges in flight per warp.
__global__ void fused_l1_kernel(const float* __restrict__ att1,
                                const float* __restrict__ b1,
                                const float* __restrict__ W2l,
                                const float* __restrict__ W2r) {
    int dst = (blockIdx.x * blockDim.x + threadIdx.x) >> 5;
    if (dst >= N_NODES) return;
    int lane = threadIdx.x & 31;
    int c0 = lane * 4;

    float4 b  = *(const float4*)(g_xr1 + (size_t)dst * 128 + c0);
    float4 at = *(const float4*)(att1 + c0);

    float4 acc = make_float4(0.f, 0.f, 0.f, 0.f);
    float denom = 0.f;

    int rs = g_rowptr[dst], re = g_rowptr[dst + 1];
    for (int i0 = rs; i0 < re; i0 += 32) {
        int n = re - i0; if (n > 32) n = 32;
        int sidx = (i0 + lane < re) ? g_csr_src[i0 + lane] : 0;
        int j = 0;
        for (; j + 8 <= n; j += 8) {
            float4 A[8];
            float  P[8];
#pragma unroll
            for (int u = 0; u < 8; u++) {
                int s = __shfl_sync(FULL, sidx, j + u);
                A[u] = *(const float4*)(g_xl1 + (size_t)s * 128 + c0);
            }
#pragma unroll
            for (int u = 0; u < 8; u++)
                P[u] = at.x * lrelu(A[u].x + b.x) + at.y * lrelu(A[u].y + b.y)
                     + at.z * lrelu(A[u].z + b.z) + at.w * lrelu(A[u].w + b.w);
#pragma unroll
            for (int s = 8; s; s >>= 1) {   // 16-lane groups => per-head sums
#pragma unroll
                for (int u = 0; u < 8; u++) P[u] += __shfl_xor_sync(FULL, P[u], s);
            }
#pragma unroll
            for (int u = 0; u < 8; u++) {
                float e = __expf(P[u]);
                denom += e;
                acc.x += e * A[u].x; acc.y += e * A[u].y;
                acc.z += e * A[u].z; acc.w += e * A[u].w;
            }
        }
        for (; j + 4 <= n; j += 4) {
            float4 A[4];
            float  P[4];
#pragma unroll
            for (int u = 0; u < 4; u++) {
                int s = __shfl_sync(FULL, sidx, j + u);
                A[u] = *(const float4*)(g_xl1 + (size_t)s * 128 + c0);
            }
#pragma unroll
            for (int u = 0; u < 4; u++)
                P[u] = at.x * lrelu(A[u].x + b.x) + at.y * lrelu(A[u].y + b.y)
                     + at.z * lrelu(A[u].z + b.z) + at.w * lrelu(A[u].w + b.w);
#pragma unroll
            for (int s = 8; s; s >>= 1) {
#pragma unroll
                for (int u = 0; u < 4; u++) P[u] += __shfl_xor_sync(FULL, P[u], s);
            }
#pragma unroll
            for (int u = 0; u < 4; u++) {
                float e = __expf(P[u]);
                denom += e;
                acc.x += e * A[u].x; acc.y += e * A[u].y;
                acc.z += e * A[u].z; acc.w += e * A[u].w;
            }
        }
        for (; j < n; j++) {
            int src = __shfl_sync(FULL, sidx, j);
            float4 a = *(const float4*)(g_xl1 + (size_t)src * 128 + c0);
            float p = at.x * lrelu(a.x + b.x) + at.y * lrelu(a.y + b.y)
                    + at.z * lrelu(a.z + b.z) + at.w * lrelu(a.w + b.w);
#pragma unroll
            for (int s = 8; s; s >>= 1) p += __shfl_xor_sync(FULL, p, s);
            float ea = __expf(p);
            denom += ea;
            acc.x += ea * a.x; acc.y += ea * a.y;
            acc.z += ea * a.z; acc.w += ea * a.w;
        }
    }

    float w = __fdividef(1.f, denom + 1e-16f);
    float4 bias = *(const float4*)(b1 + c0);
    float ov[4];
    ov[0] = acc.x * w + bias.x;
    ov[1] = acc.y * w + bias.y;
    ov[2] = acc.z * w + bias.z;
    ov[3] = acc.w * w + bias.w;
#pragma unroll
    for (int j = 0; j < 4; j++)
        ov[j] = ov[j] > 0.f ? ov[j] : (__expf(ov[j]) - 1.f);   // ELU

    // fused GEMM2: pl[c] = sum_k ov[k] * W2l[k][c] (k = c0..c0+3 per lane)
    float pl0 = 0.f, pl1 = 0.f, pl2 = 0.f, pr0 = 0.f, pr1 = 0.f, pr2 = 0.f;
#pragma unroll
    for (int j = 0; j < 4; j++) {
        int k = c0 + j;
        pl0 += ov[j] * W2l[k * 3 + 0];
        pl1 += ov[j] * W2l[k * 3 + 1];
        pl2 += ov[j] * W2l[k * 3 + 2];
        pr0 += ov[j] * W2r[k * 3 + 0];
        pr1 += ov[j] * W2r[k * 3 + 1];
        pr2 += ov[j] * W2r[k * 3 + 2];
    }
#pragma unroll
    for (int s = 16; s; s >>= 1) {
        pl0 += __shfl_xor_sync(FULL, pl0, s);
        pl1 += __shfl_xor_sync(FULL, pl1, s);
        pl2 += __shfl_xor_sync(FULL, pl2, s);
        pr0 += __shfl_xor_sync(FULL, pr0, s);
        pr1 += __shfl_xor_sync(FULL, pr1, s);
        pr2 += __shfl_xor_sync(FULL, pr2, s);
    }
    if (lane == 0) {
        *(float4*)(g_xl2 + dst * 4) = make_float4(pl0, pl1, pl2, 0.f);
        *(float4*)(g_xr2 + dst * 4) = make_float4(pr0, pr1, pr2, 0.f);
    }
}

// ---------------- fused layer 2 + pool scatter: warp per dst ----------------
__global__ void fused_l2_kernel(const float* __restrict__ att2,
                                const float* __restrict__ b2,
                                const int* __restrict__ batch) {
    int dst = (blockIdx.x * blockDim.x + threadIdx.x) >> 5;
    if (dst >= N_NODES) return;
    int lane = threadIdx.x & 31;
    float a0 = att2[0], a1 = att2[1], a2 = att2[2];
    float4 rv = *(const float4*)(g_xr2 + dst * 4);
    float d = 0.f, m0 = 0.f, m1 = 0.f, m2 = 0.f;
    int rs = g_rowptr[dst], re = g_rowptr[dst + 1];
    for (int i = rs + lane; i < re; i += 32) {
        int src = g_csr_src[i];
        float4 sv = *(const float4*)(g_xl2 + src * 4);
        float p = a0 * lrelu(sv.x + rv.x) + a1 * lrelu(sv.y + rv.y) + a2 * lrelu(sv.z + rv.z);
        float ea = __expf(p);
        d += ea; m0 += ea * sv.x; m1 += ea * sv.y; m2 += ea * sv.z;
    }
#pragma unroll
    for (int o = 16; o; o >>= 1) {
        d  += __shfl_xor_sync(FULL, d, o);
        m0 += __shfl_xor_sync(FULL, m0, o);
        m1 += __shfl_xor_sync(FULL, m1, o);
        m2 += __shfl_xor_sync(FULL, m2, o);
    }
    if (lane == 0) {
        float w = __fdividef(1.f, d + 1e-16f);
        int g = batch[dst];
        atomicAdd(&g_pool[g * 4 + 0], m0 * w + b2[0]);
        atomicAdd(&g_pool[g * 4 + 1], m1 * w + b2[1]);
        atomicAdd(&g_pool[g * 4 + 2], m2 * w + b2[2]);
    }
}

// ---------------- final MLP: thread per graph -------------------------------
__global__ void mlp_kernel(const float* __restrict__ Wr1, const float* __restrict__ br1,
                           const float* __restrict__ Wr2, const float* __restrict__ br2,
                           float* __restrict__ out) {
    int g = threadIdx.x;
    if (g >= N_GRAPHS) return;
    float cnt = g_pool[g * 4 + 3];
    float inv = 1.f / fmaxf(cnt, 1.f);
    float v0 = g_pool[g * 4 + 0] * inv;
    float v1 = g_pool[g * 4 + 1] * inv;
    float v2 = g_pool[g * 4 + 2] * inv;
    float o0 = br2[0], o1 = br2[1], o2 = br2[2];
#pragma unroll 8
    for (int j = 0; j < 64; j++) {
        float hj = v0 * Wr1[j] + v1 * Wr1[64 + j] + v2 * Wr1[128 + j] + br1[j];
        hj = fmaxf(hj, 0.f);
        o0 += hj * Wr2[j * 3 + 0];
        o1 += hj * Wr2[j * 3 + 1];
        o2 += hj * Wr2[j * 3 + 2];
    }
    out[g * 3 + 0] = o0;
    out[g * 3 + 1] = o1;
    out[g * 3 + 2] = o2;
}

// ---------------- stream/event handles (created at static init) -------------
struct SideStream {
    cudaStream_t s;
    cudaEvent_t evFork, evJoin;
    SideStream() {
        cudaStreamCreateWithFlags(&s, cudaStreamNonBlocking);
        cudaEventCreateWithFlags(&evFork, cudaEventDisableTiming);
        cudaEventCreateWithFlags(&evJoin, cudaEventDisableTiming);
    }
};
static SideStream g_ss;

// ---------------- launch ----------------------------------------------------
extern "C" void kernel_launch(void* const* d_in, const int* in_sizes, int n_in,
                              void* d_out, int out_size) {
    (void)in_sizes; (void)n_in; (void)out_size;
    const float* x    = (const float*)d_in[0];
    const int*   ei   = (const int*)  d_in[1];
    const int*   batch= (const int*)  d_in[2];
    const float* W1l  = (const float*)d_in[3];
    const float* W1r  = (const float*)d_in[4];
    const float* att1 = (const float*)d_in[5];
    const float* b1   = (const float*)d_in[6];
    const float* W2l  = (const float*)d_in[7];
    const float* W2r  = (const float*)d_in[8];
    const float* att2 = (const float*)d_in[9];
    const float* b2   = (const float*)d_in[10];
    const float* Wr1  = (const float*)d_in[11];
    const float* br1  = (const float*)d_in[12];
    const float* Wr2  = (const float*)d_in[13];
    const float* br2  = (const float*)d_in[14];
    float* out = (float*)d_out;

    // fork: gemm1 runs concurrently with the CSR build
    cudaEventRecord(g_ss.evFork, 0);
    cudaStreamWaitEvent(g_ss.s, g_ss.evFork, 0);
    {
        dim3 grid((N_NODES + 127) / 128, 2);
        gemm1_kernel<<<grid, 256, 0, g_ss.s>>>(x, W1l, W1r);
    }
    cudaEventRecord(g_ss.evJoin, g_ss.s);

    init_kernel<<<(N_NODES + 255) / 256, 256>>>();
    csr_count_kernel<<<(ET + 255) / 256, 256>>>(ei, batch);
    scan_local_kernel<<<NB_SCAN, 256>>>();
    scan_apply_kernel<<<NB_SCAN, 256>>>();
    csr_fill_kernel<<<(ET + 255) / 256, 256>>>(ei);

    // join: fused_l1 needs both gemm1 output and CSR
    cudaStreamWaitEvent(0, g_ss.evJoin, 0);
    {
        long long t = (long long)N_NODES * 32;
        fused_l1_kernel<<<(unsigned)((t + 255) / 256), 256>>>(att1, b1, W2l, W2r);
        fused_l2_kernel<<<(unsigned)((t + 255) / 256), 256>>>(att2, b2, batch);
    }
    mlp_kernel<<<1, 64>>>(Wr1, br1, Wr2, br2, out);
}

// round 11
// speedup vs baseline: 1.1990x; 1.0004x over previous
#include <cuda_runtime.h>

#define N_NODES 50000
#define N_EDGES 800000
#define ET (N_EDGES + N_NODES)   // self-loops appended
#define N_GRAPHS 64
#define FULL 0xffffffffu
#define NB_SCAN ((N_NODES + 255) / 256)   // 196
#define L2_BLOCKS (N_NODES / 16)          // 3125 blocks, 2 dst/warp * 8 warps

// ---------------- scratch (device globals; zero at module load) ------------
__device__ __align__(16) float g_xl1[N_NODES * 128];
__device__ __align__(16) float g_xr1[N_NODES * 128];
__device__ __align__(16) float g_xl2[N_NODES * 4];
__device__ __align__(16) float g_xr2[N_NODES * 4];
__device__ int g_cnt[N_NODES];          // invariant: zero at kernel_launch entry
__device__ int g_rowptr[N_NODES + 1];
__device__ int g_cursor[N_NODES];
__device__ int g_csr_src[ET];
__device__ int g_bsum[NB_SCAN];
__device__ float g_pool[N_GRAPHS * 4];  // invariant: zero at kernel_launch entry
__device__ int g_done;                  // invariant: zero at kernel_launch entry

__device__ __forceinline__ float lrelu(float v) { return v > 0.f ? v : 0.2f * v; }

// f32x2 packed FMA (sm_100+): d = a*b + d, elementwise on packed pairs
#define FMA2(d, a, b) asm("fma.rn.f32x2 %0, %1, %2, %0;" : "+l"(d) : "l"(a), "l"(b))
__device__ __forceinline__ unsigned long long pack2(float lo, float hi) {
    unsigned long long r;
    asm("mov.b64 %0, {%1, %2};" : "=l"(r) : "f"(lo), "f"(hi));
    return r;
}
__device__ __forceinline__ void unpack2(unsigned long long v, float& lo, float& hi) {
    asm("mov.b64 {%0, %1}, %2;" : "=f"(lo), "=f"(hi) : "l"(v));
}

// ---------------- CSR: count incoming edges per dst (+ per-graph node cnt) -
__global__ void csr_count_kernel(const int* __restrict__ ei,
                                 const int* __restrict__ batch) {
    int e = blockIdx.x * blockDim.x + threadIdx.x;
    if (e < ET) {
        int dst = (e < N_EDGES) ? ei[N_EDGES + e] : (e - N_EDGES);
        atomicAdd(&g_cnt[dst], 1);
    }
    if (e < N_NODES) atomicAdd(&g_pool[batch[e] * 4 + 3], 1.f);
}

// ---------------- scan phase 1: per-block exclusive scan --------------------
__global__ void scan_local_kernel() {
    __shared__ int sh[256];
    int t = threadIdx.x;
    int i = blockIdx.x * 256 + t;
    int v = (i < N_NODES) ? g_cnt[i] : 0;
    sh[t] = v;
    __syncthreads();
#pragma unroll
    for (int off = 1; off < 256; off <<= 1) {
        int u = (t >= off) ? sh[t - off] : 0;
        __syncthreads();
        sh[t] += u;
        __syncthreads();
    }
    if (i < N_NODES) g_rowptr[i] = sh[t] - v;          // exclusive within block
    if (t == 255) g_bsum[blockIdx.x] = sh[255];        // block total
}

// ---------------- scan phase 2: apply + restore g_cnt invariant -------------
__global__ void scan_apply_kernel() {
    __shared__ int sh[256];
    int t = threadIdx.x, bid = blockIdx.x;
    sh[t] = (t < bid) ? g_bsum[t] : 0;   // NB_SCAN = 196 <= 256
    __syncthreads();
#pragma unroll
    for (int off = 128; off; off >>= 1) {
        if (t < off) sh[t] += sh[t + off];
        __syncthreads();
    }
    int boff = sh[0];
    int i = bid * 256 + t;
    if (i < N_NODES) {
        int r = g_rowptr[i] + boff;
        g_rowptr[i] = r;
        g_cursor[i] = r;
        g_cnt[i] = 0;                    // g_cnt dead after this: restore invariant
    }
    if (i == 0) g_rowptr[N_NODES] = ET;
}

// ---------------- CSR: scatter src ids into slots --------------------------
__global__ void csr_fill_kernel(const int* __restrict__ ei) {
    int e = blockIdx.x * blockDim.x + threadIdx.x;
    if (e >= ET) return;
    int src, dst;
    if (e < N_EDGES) { src = ei[e]; dst = ei[N_EDGES + e]; }
    else             { src = dst = e - N_EDGES; }
    int pos = atomicAdd(&g_cursor[dst], 1);
    g_csr_src[pos] = src;
}

// ---------------- GEMM1 v3: 128x128 tile, K-chunked smem, reg-tiled --------
#define G3_KC 32
#define G3_PAD 132
__global__ void __launch_bounds__(256, 2)
gemm1_kernel(const float* __restrict__ x,
             const float* __restrict__ Wl,
             const float* __restrict__ Wr) {
    __shared__ float xs[G3_KC][G3_PAD];
    __shared__ float ws[G3_KC][G3_PAD];
    int row0 = blockIdx.x * 128;
    const float* W = blockIdx.y ? Wr : Wl;
    int tid = threadIdx.x;
    int rg = tid >> 3;
    int cg = tid & 7;

    unsigned long long acc[4][8];
#pragma unroll
    for (int r = 0; r < 4; r++)
#pragma unroll
        for (int c = 0; c < 8; c++) acc[r][c] = 0ull;

    for (int k0 = 0; k0 < 128; k0 += G3_KC) {
        {
            int r = tid >> 1;
            int kb = (tid & 1) * 16;
            int grow = row0 + r;
#pragma unroll
            for (int j4 = 0; j4 < 4; j4++) {
                float4 v = make_float4(0.f, 0.f, 0.f, 0.f);
                if (grow < N_NODES)
                    v = *(const float4*)(x + (size_t)grow * 128 + k0 + kb + j4 * 4);
                xs[kb + j4 * 4 + 0][r] = v.x;
                xs[kb + j4 * 4 + 1][r] = v.y;
                xs[kb + j4 * 4 + 2][r] = v.z;
                xs[kb + j4 * 4 + 3][r] = v.w;
            }
        }
        {
            int k = tid >> 3;
            int cs = (tid & 7) * 16;
#pragma unroll
            for (int j4 = 0; j4 < 4; j4++) {
                float4 v = *(const float4*)(W + (size_t)(k0 + k) * 128 + cs + j4 * 4);
                *(float4*)&ws[k][cs + j4 * 4] = v;
            }
        }
        __syncthreads();
#pragma unroll 4
        for (int k = 0; k < G3_KC; k++) {
            float4 av = *(const float4*)&xs[k][rg * 4];
            unsigned long long ap[4];
            ap[0] = pack2(av.x, av.x);
            ap[1] = pack2(av.y, av.y);
            ap[2] = pack2(av.z, av.z);
            ap[3] = pack2(av.w, av.w);
#pragma unroll
            for (int s = 0; s < 4; s++) {
                float4 bv = *(const float4*)&ws[k][cg * 4 + s * 32];
                unsigned long long b0 = pack2(bv.x, bv.y);
                unsigned long long b1 = pack2(bv.z, bv.w);
#pragma unroll
                for (int r = 0; r < 4; r++) {
                    FMA2(acc[r][2 * s + 0], ap[r], b0);
                    FMA2(acc[r][2 * s + 1], ap[r], b1);
                }
            }
        }
        __syncthreads();
    }

    float* outbuf = blockIdx.y ? g_xr1 : g_xl1;
#pragma unroll
    for (int r = 0; r < 4; r++) {
        int grow = row0 + rg * 4 + r;
        if (grow >= N_NODES) continue;
#pragma unroll
        for (int s = 0; s < 4; s++) {
            float4 o;
            unpack2(acc[r][2 * s + 0], o.x, o.y);
            unpack2(acc[r][2 * s + 1], o.z, o.w);
            *(float4*)(outbuf + (size_t)grow * 128 + cg * 4 + s * 32) = o;
        }
    }
}

// ---------------- fused layer1 + bias + ELU + GEMM2: warp per dst ----------
// lanes 0-15 head0 (ch 0..63), 16-31 head1. 8 edges in flight per warp.
__global__ void fused_l1_kernel(const float* __restrict__ att1,
                                const float* __restrict__ b1,
                                const float* __restrict__ W2l,
                                const float* __restrict__ W2r) {
    int dst = (blockIdx.x * blockDim.x + threadIdx.x) >> 5;
    if (dst >= N_NODES) return;
    int lane = threadIdx.x & 31;
    int c0 = lane * 4;

    float4 b  = *(const float4*)(g_xr1 + (size_t)dst * 128 + c0);
    float4 at = *(const float4*)(att1 + c0);

    float4 acc = make_float4(0.f, 0.f, 0.f, 0.f);
    float denom = 0.f;

    int rs = g_rowptr[dst], re = g_rowptr[dst + 1];
    for (int i0 = rs; i0 < re; i0 += 32) {
        int n = re - i0; if (n > 32) n = 32;
        int sidx = (i0 + lane < re) ? g_csr_src[i0 + lane] : 0;
        int j = 0;
        for (; j + 8 <= n; j += 8) {
            float4 A[8];
            float  P[8];
#pragma unroll
            for (int u = 0; u < 8; u++) {
                int s = __shfl_sync(FULL, sidx, j + u);
                A[u] = *(const float4*)(g_xl1 + (size_t)s * 128 + c0);
            }
#pragma unroll
            for (int u = 0; u < 8; u++)
                P[u] = at.x * lrelu(A[u].x + b.x) + at.y * lrelu(A[u].y + b.y)
                     + at.z * lrelu(A[u].z + b.z) + at.w * lrelu(A[u].w + b.w);
#pragma unroll
            for (int s = 8; s; s >>= 1) {   // 16-lane groups => per-head sums
#pragma unroll
                for (int u = 0; u < 8; u++) P[u] += __shfl_xor_sync(FULL, P[u], s);
            }
#pragma unroll
            for (int u = 0; u < 8; u++) {
                float e = __expf(P[u]);
                denom += e;
                acc.x += e * A[u].x; acc.y += e * A[u].y;
                acc.z += e * A[u].z; acc.w += e * A[u].w;
            }
        }
        for (; j + 4 <= n; j += 4) {
            float4 A[4];
            float  P[4];
#pragma unroll
            for (int u = 0; u < 4; u++) {
                int s = __shfl_sync(FULL, sidx, j + u);
                A[u] = *(const float4*)(g_xl1 + (size_t)s * 128 + c0);
            }
#pragma unroll
            for (int u = 0; u < 4; u++)
                P[u] = at.x * lrelu(A[u].x + b.x) + at.y * lrelu(A[u].y + b.y)
                     + at.z * lrelu(A[u].z + b.z) + at.w * lrelu(A[u].w + b.w);
#pragma unroll
            for (int s = 8; s; s >>= 1) {
#pragma unroll
                for (int u = 0; u < 4; u++) P[u] += __shfl_xor_sync(FULL, P[u], s);
            }
#pragma unroll
            for (int u = 0; u < 4; u++) {
                float e = __expf(P[u]);
                denom += e;
                acc.x += e * A[u].x; acc.y += e * A[u].y;
                acc.z += e * A[u].z; acc.w += e * A[u].w;
            }
        }
        for (; j < n; j++) {
            int src = __shfl_sync(FULL, sidx, j);
            float4 a = *(const float4*)(g_xl1 + (size_t)src * 128 + c0);
            float p = at.x * lrelu(a.x + b.x) + at.y * lrelu(a.y + b.y)
                    + at.z * lrelu(a.z + b.z) + at.w * lrelu(a.w + b.w);
#pragma unroll
            for (int s = 8; s; s >>= 1) p += __shfl_xor_sync(FULL, p, s);
            float ea = __expf(p);
            denom += ea;
            acc.x += ea * a.x; acc.y += ea * a.y;
            acc.z += ea * a.z; acc.w += ea * a.w;
        }
    }

    float w = __fdividef(1.f, denom + 1e-16f);
    float4 bias = *(const float4*)(b1 + c0);
    float ov[4];
    ov[0] = acc.x * w + bias.x;
    ov[1] = acc.y * w + bias.y;
    ov[2] = acc.z * w + bias.z;
    ov[3] = acc.w * w + bias.w;
#pragma unroll
    for (int j = 0; j < 4; j++)
        ov[j] = ov[j] > 0.f ? ov[j] : (__expf(ov[j]) - 1.f);   // ELU

    float pl0 = 0.f, pl1 = 0.f, pl2 = 0.f, pr0 = 0.f, pr1 = 0.f, pr2 = 0.f;
#pragma unroll
    for (int j = 0; j < 4; j++) {
        int k = c0 + j;
        pl0 += ov[j] * W2l[k * 3 + 0];
        pl1 += ov[j] * W2l[k * 3 + 1];
        pl2 += ov[j] * W2l[k * 3 + 2];
        pr0 += ov[j] * W2r[k * 3 + 0];
        pr1 += ov[j] * W2r[k * 3 + 1];
        pr2 += ov[j] * W2r[k * 3 + 2];
    }
#pragma unroll
    for (int s = 16; s; s >>= 1) {
        pl0 += __shfl_xor_sync(FULL, pl0, s);
        pl1 += __shfl_xor_sync(FULL, pl1, s);
        pl2 += __shfl_xor_sync(FULL, pl2, s);
        pr0 += __shfl_xor_sync(FULL, pr0, s);
        pr1 += __shfl_xor_sync(FULL, pr1, s);
        pr2 += __shfl_xor_sync(FULL, pr2, s);
    }
    if (lane == 0) {
        *(float4*)(g_xl2 + dst * 4) = make_float4(pl0, pl1, pl2, 0.f);
        *(float4*)(g_xr2 + dst * 4) = make_float4(pr0, pr1, pr2, 0.f);
    }
}

// ---------------- fused layer2 + pool + (last block) MLP --------------------
// 2 dsts per warp: lanes 0-15 -> dst0, lanes 16-31 -> dst1.
__global__ void fused_l2_mlp_kernel(const float* __restrict__ att2,
                                    const float* __restrict__ b2,
                                    const int* __restrict__ batch,
                                    const float* __restrict__ Wr1,
                                    const float* __restrict__ br1,
                                    const float* __restrict__ Wr2,
                                    const float* __restrict__ br2,
                                    float* __restrict__ out) {
    int warp_g = (blockIdx.x * blockDim.x + threadIdx.x) >> 5;
    int lane = threadIdx.x & 31;
    int sl = lane & 15;
    int dst = warp_g * 2 + (lane >> 4);

    if (dst < N_NODES) {
        float a0 = att2[0], a1 = att2[1], a2 = att2[2];
        float4 rv = *(const float4*)(g_xr2 + dst * 4);
        float d = 0.f, m0 = 0.f, m1 = 0.f, m2 = 0.f;
        int rs = g_rowptr[dst], re = g_rowptr[dst + 1];
        for (int i = rs + sl; i < re; i += 16) {
            int src = g_csr_src[i];
            float4 sv = *(const float4*)(g_xl2 + src * 4);
            float p = a0 * lrelu(sv.x + rv.x) + a1 * lrelu(sv.y + rv.y)
                    + a2 * lrelu(sv.z + rv.z);
            float ea = __expf(p);
            d += ea; m0 += ea * sv.x; m1 += ea * sv.y; m2 += ea * sv.z;
        }
#pragma unroll
        for (int o = 8; o; o >>= 1) {   // reduce within 16-lane group
            d  += __shfl_xor_sync(FULL, d, o);
            m0 += __shfl_xor_sync(FULL, m0, o);
            m1 += __shfl_xor_sync(FULL, m1, o);
            m2 += __shfl_xor_sync(FULL, m2, o);
        }
        if (sl == 0) {
            float w = __fdividef(1.f, d + 1e-16f);
            int g = batch[dst];
            atomicAdd(&g_pool[g * 4 + 0], m0 * w + b2[0]);
            atomicAdd(&g_pool[g * 4 + 1], m1 * w + b2[1]);
            atomicAdd(&g_pool[g * 4 + 2], m2 * w + b2[2]);
        }
    }

    // ---- last-block ticket: the final block to finish runs the MLP ----
    __syncthreads();
    __shared__ int s_last;
    if (threadIdx.x == 0) {
        __threadfence();
        int ticket = atomicAdd(&g_done, 1);
        s_last = (ticket == gridDim.x - 1) ? 1 : 0;
    }
    __syncthreads();
    if (!s_last) return;
    __threadfence();   // acquire: all pool atomics now visible

    int g = threadIdx.x;
    if (g < N_GRAPHS) {
        float cnt = g_pool[g * 4 + 3];
        float inv = 1.f / fmaxf(cnt, 1.f);
        float v0 = g_pool[g * 4 + 0] * inv;
        float v1 = g_pool[g * 4 + 1] * inv;
        float v2 = g_pool[g * 4 + 2] * inv;
        float o0 = br2[0], o1 = br2[1], o2 = br2[2];
#pragma unroll 8
        for (int j = 0; j < 64; j++) {
            float hj = v0 * Wr1[j] + v1 * Wr1[64 + j] + v2 * Wr1[128 + j] + br1[j];
            hj = fmaxf(hj, 0.f);
            o0 += hj * Wr2[j * 3 + 0];
            o1 += hj * Wr2[j * 3 + 1];
            o2 += hj * Wr2[j * 3 + 2];
        }
        out[g * 3 + 0] = o0;
        out[g * 3 + 1] = o1;
        out[g * 3 + 2] = o2;
    }
    __syncthreads();
    // restore invariants for next replay (pool read is complete)
    if (threadIdx.x < N_GRAPHS * 4) g_pool[threadIdx.x] = 0.f;
    if (threadIdx.x == 0) g_done = 0;
}

// ---------------- stream/event handles (created at static init) -------------
struct SideStream {
    cudaStream_t s;
    cudaEvent_t evFork, evJoin;
    SideStream() {
        cudaStreamCreateWithFlags(&s, cudaStreamNonBlocking);
        cudaEventCreateWithFlags(&evFork, cudaEventDisableTiming);
        cudaEventCreateWithFlags(&evJoin, cudaEventDisableTiming);
    }
};
static SideStream g_ss;

// ---------------- launch ----------------------------------------------------
extern "C" void kernel_launch(void* const* d_in, const int* in_sizes, int n_in,
                              void* d_out, int out_size) {
    (void)in_sizes; (void)n_in; (void)out_size;
    const float* x    = (const float*)d_in[0];
    const int*   ei   = (const int*)  d_in[1];
    const int*   batch= (const int*)  d_in[2];
    const float* W1l  = (const float*)d_in[3];
    const float* W1r  = (const float*)d_in[4];
    const float* att1 = (const float*)d_in[5];
    const float* b1   = (const float*)d_in[6];
    const float* W2l  = (const float*)d_in[7];
    const float* W2r  = (const float*)d_in[8];
    const float* att2 = (const float*)d_in[9];
    const float* b2   = (const float*)d_in[10];
    const float* Wr1  = (const float*)d_in[11];
    const float* br1  = (const float*)d_in[12];
    const float* Wr2  = (const float*)d_in[13];
    const float* br2  = (const float*)d_in[14];
    float* out = (float*)d_out;

    // fork: gemm1 (launch #1) runs concurrently with the CSR build
    cudaEventRecord(g_ss.evFork, 0);
    cudaStreamWaitEvent(g_ss.s, g_ss.evFork, 0);
    {
        dim3 grid((N_NODES + 127) / 128, 2);
        gemm1_kernel<<<grid, 256, 0, g_ss.s>>>(x, W1l, W1r);
    }
    cudaEventRecord(g_ss.evJoin, g_ss.s);

    csr_count_kernel<<<(ET + 255) / 256, 256>>>(ei, batch);   // #2
    scan_local_kernel<<<NB_SCAN, 256>>>();                    // #3
    scan_apply_kernel<<<NB_SCAN, 256>>>();                    // #4 (+ zero g_cnt)
    csr_fill_kernel<<<(ET + 255) / 256, 256>>>(ei);           // #5

    // join: fused_l1 needs both gemm1 output and CSR
    cudaStreamWaitEvent(0, g_ss.evJoin, 0);
    {
        long long t = (long long)N_NODES * 32;
        fused_l1_kernel<<<(unsigned)((t + 255) / 256), 256>>>(att1, b1, W2l, W2r); // #6
    }
    fused_l2_mlp_kernel<<<L2_BLOCKS, 256>>>(att2, b2, batch,
                                            Wr1, br1, Wr2, br2, out);              // #7
}

// round 12
// speedup vs baseline: 1.2291x; 1.0251x over previous
#include <cuda_runtime.h>

#define N_NODES 50000
#define N_EDGES 800000
#define ET (N_EDGES + N_NODES)   // self-loops appended
#define N_GRAPHS 64
#define FULL 0xffffffffu
#define NB_SCAN ((N_NODES + 255) / 256)   // 196
#define L2_BLOCKS (N_NODES / 16)          // 3125 blocks, 2 dst/warp * 8 warps

// ---------------- scratch (device globals; zero at module load) ------------
__device__ __align__(16) float g_xl1[N_NODES * 128];
__device__ __align__(16) float g_xr1[N_NODES * 128];
__device__ __align__(16) float g_xl2[N_NODES * 4];
__device__ __align__(16) float g_xr2[N_NODES * 4];
__device__ int g_cnt[N_NODES];          // invariant: zero at kernel_launch entry
__device__ int g_rowptr[N_NODES + 1];
__device__ int g_cursor[N_NODES];
__device__ int g_csr_src[ET];
__device__ int g_bsum[NB_SCAN];
__device__ float g_pool[N_GRAPHS * 4];  // invariant: zero at kernel_launch entry
__device__ int g_done;                  // invariant: zero at kernel_launch entry

__device__ __forceinline__ float lrelu(float v) { return v > 0.f ? v : 0.2f * v; }

// f32x2 packed FMA (sm_100+): d = a*b + d, elementwise on packed pairs
#define FMA2(d, a, b) asm("fma.rn.f32x2 %0, %1, %2, %0;" : "+l"(d) : "l"(a), "l"(b))
__device__ __forceinline__ unsigned long long pack2(float lo, float hi) {
    unsigned long long r;
    asm("mov.b64 %0, {%1, %2};" : "=l"(r) : "f"(lo), "f"(hi));
    return r;
}
__device__ __forceinline__ void unpack2(unsigned long long v, float& lo, float& hi) {
    asm("mov.b64 {%0, %1}, %2;" : "=f"(lo), "=f"(hi) : "l"(v));
}

// ---------------- CSR: count incoming edges per dst (+ per-graph node cnt) -
__global__ void csr_count_kernel(const int* __restrict__ ei,
                                 const int* __restrict__ batch) {
    int e = blockIdx.x * blockDim.x + threadIdx.x;
    if (e < ET) {
        int dst = (e < N_EDGES) ? ei[N_EDGES + e] : (e - N_EDGES);
        atomicAdd(&g_cnt[dst], 1);
    }
    if (e < N_NODES) atomicAdd(&g_pool[batch[e] * 4 + 3], 1.f);
}

// ---------------- scan phase 1: per-block exclusive scan --------------------
__global__ void scan_local_kernel() {
    __shared__ int sh[256];
    int t = threadIdx.x;
    int i = blockIdx.x * 256 + t;
    int v = (i < N_NODES) ? g_cnt[i] : 0;
    sh[t] = v;
    __syncthreads();
#pragma unroll
    for (int off = 1; off < 256; off <<= 1) {
        int u = (t >= off) ? sh[t - off] : 0;
        __syncthreads();
        sh[t] += u;
        __syncthreads();
    }
    if (i < N_NODES) g_rowptr[i] = sh[t] - v;          // exclusive within block
    if (t == 255) g_bsum[blockIdx.x] = sh[255];        // block total
}

// ---------------- scan phase 2: apply + restore g_cnt invariant -------------
__global__ void scan_apply_kernel() {
    __shared__ int sh[256];
    int t = threadIdx.x, bid = blockIdx.x;
    sh[t] = (t < bid) ? g_bsum[t] : 0;   // NB_SCAN = 196 <= 256
    __syncthreads();
#pragma unroll
    for (int off = 128; off; off >>= 1) {
        if (t < off) sh[t] += sh[t + off];
        __syncthreads();
    }
    int boff = sh[0];
    int i = bid * 256 + t;
    if (i < N_NODES) {
        int r = g_rowptr[i] + boff;
        g_rowptr[i] = r;
        g_cursor[i] = r;
        g_cnt[i] = 0;                    // g_cnt dead after this: restore invariant
    }
    if (i == 0) g_rowptr[N_NODES] = ET;
}

// ---------------- CSR: scatter src ids into slots --------------------------
__global__ void csr_fill_kernel(const int* __restrict__ ei) {
    int e = blockIdx.x * blockDim.x + threadIdx.x;
    if (e >= ET) return;
    int src, dst;
    if (e < N_EDGES) { src = ei[e]; dst = ei[N_EDGES + e]; }
    else             { src = dst = e - N_EDGES; }
    int pos = atomicAdd(&g_cursor[dst], 1);
    g_csr_src[pos] = src;
}

// ---------------- GEMM1 v3: 128x128 tile, K-chunked smem, reg-tiled --------
#define G3_KC 32
#define G3_PAD 132
__global__ void __launch_bounds__(256, 2)
gemm1_kernel(const float* __restrict__ x,
             const float* __restrict__ Wl,
             const float* __restrict__ Wr) {
    __shared__ float xs[G3_KC][G3_PAD];
    __shared__ float ws[G3_KC][G3_PAD];
    int row0 = blockIdx.x * 128;
    const float* W = blockIdx.y ? Wr : Wl;
    int tid = threadIdx.x;
    int rg = tid >> 3;
    int cg = tid & 7;

    unsigned long long acc[4][8];
#pragma unroll
    for (int r = 0; r < 4; r++)
#pragma unroll
        for (int c = 0; c < 8; c++) acc[r][c] = 0ull;

    for (int k0 = 0; k0 < 128; k0 += G3_KC) {
        {
            int r = tid >> 1;
            int kb = (tid & 1) * 16;
            int grow = row0 + r;
#pragma unroll
            for (int j4 = 0; j4 < 4; j4++) {
                float4 v = make_float4(0.f, 0.f, 0.f, 0.f);
                if (grow < N_NODES)
                    v = *(const float4*)(x + (size_t)grow * 128 + k0 + kb + j4 * 4);
                xs[kb + j4 * 4 + 0][r] = v.x;
                xs[kb + j4 * 4 + 1][r] = v.y;
                xs[kb + j4 * 4 + 2][r] = v.z;
                xs[kb + j4 * 4 + 3][r] = v.w;
            }
        }
        {
            int k = tid >> 3;
            int cs = (tid & 7) * 16;
#pragma unroll
            for (int j4 = 0; j4 < 4; j4++) {
                float4 v = *(const float4*)(W + (size_t)(k0 + k) * 128 + cs + j4 * 4);
                *(float4*)&ws[k][cs + j4 * 4] = v;
            }
        }
        __syncthreads();
#pragma unroll 4
        for (int k = 0; k < G3_KC; k++) {
            float4 av = *(const float4*)&xs[k][rg * 4];
            unsigned long long ap[4];
            ap[0] = pack2(av.x, av.x);
            ap[1] = pack2(av.y, av.y);
            ap[2] = pack2(av.z, av.z);
            ap[3] = pack2(av.w, av.w);
#pragma unroll
            for (int s = 0; s < 4; s++) {
                float4 bv = *(const float4*)&ws[k][cg * 4 + s * 32];
                unsigned long long b0 = pack2(bv.x, bv.y);
                unsigned long long b1 = pack2(bv.z, bv.w);
#pragma unroll
                for (int r = 0; r < 4; r++) {
                    FMA2(acc[r][2 * s + 0], ap[r], b0);
                    FMA2(acc[r][2 * s + 1], ap[r], b1);
                }
            }
        }
        __syncthreads();
    }

    float* outbuf = blockIdx.y ? g_xr1 : g_xl1;
#pragma unroll
    for (int r = 0; r < 4; r++) {
        int grow = row0 + rg * 4 + r;
        if (grow >= N_NODES) continue;
#pragma unroll
        for (int s = 0; s < 4; s++) {
            float4 o;
            unpack2(acc[r][2 * s + 0], o.x, o.y);
            unpack2(acc[r][2 * s + 1], o.z, o.w);
            *(float4*)(outbuf + (size_t)grow * 128 + cg * 4 + s * 32) = o;
        }
    }
}

// ---------------- fused layer1 + bias + ELU + GEMM2: warp per dst ----------
// lanes 0-15 head0 (ch 0..63), 16-31 head1. 6 edges in flight per warp.
// src indices come from uniform broadcast LDGs (no shfl-fed addresses).
#define L1_UN 6
__global__ void __launch_bounds__(256, 3)
fused_l1_kernel(const float* __restrict__ att1,
                const float* __restrict__ b1,
                const float* __restrict__ W2l,
                const float* __restrict__ W2r) {
    int dst = (blockIdx.x * blockDim.x + threadIdx.x) >> 5;
    if (dst >= N_NODES) return;
    int lane = threadIdx.x & 31;
    int c0 = lane * 4;

    float4 b  = *(const float4*)(g_xr1 + (size_t)dst * 128 + c0);
    float4 at = *(const float4*)(att1 + c0);

    float4 acc = make_float4(0.f, 0.f, 0.f, 0.f);
    float denom = 0.f;

    int rs = g_rowptr[dst], re = g_rowptr[dst + 1];
    int i = rs;
    for (; i + L1_UN <= re; i += L1_UN) {
        int s[L1_UN];
#pragma unroll
        for (int u = 0; u < L1_UN; u++) s[u] = g_csr_src[i + u];   // uniform bcast
        float4 A[L1_UN];
#pragma unroll
        for (int u = 0; u < L1_UN; u++)
            A[u] = *(const float4*)(g_xl1 + (size_t)s[u] * 128 + c0);
        float P[L1_UN];
#pragma unroll
        for (int u = 0; u < L1_UN; u++)
            P[u] = at.x * lrelu(A[u].x + b.x) + at.y * lrelu(A[u].y + b.y)
                 + at.z * lrelu(A[u].z + b.z) + at.w * lrelu(A[u].w + b.w);
#pragma unroll
        for (int o = 8; o; o >>= 1) {   // 16-lane groups => per-head sums
#pragma unroll
            for (int u = 0; u < L1_UN; u++) P[u] += __shfl_xor_sync(FULL, P[u], o);
        }
#pragma unroll
        for (int u = 0; u < L1_UN; u++) {
            float e = __expf(P[u]);
            denom += e;
            acc.x += e * A[u].x; acc.y += e * A[u].y;
            acc.z += e * A[u].z; acc.w += e * A[u].w;
        }
    }
    for (; i < re; i++) {
        int src = g_csr_src[i];
        float4 a = *(const float4*)(g_xl1 + (size_t)src * 128 + c0);
        float p = at.x * lrelu(a.x + b.x) + at.y * lrelu(a.y + b.y)
                + at.z * lrelu(a.z + b.z) + at.w * lrelu(a.w + b.w);
#pragma unroll
        for (int o = 8; o; o >>= 1) p += __shfl_xor_sync(FULL, p, o);
        float ea = __expf(p);
        denom += ea;
        acc.x += ea * a.x; acc.y += ea * a.y;
        acc.z += ea * a.z; acc.w += ea * a.w;
    }

    float w = __fdividef(1.f, denom + 1e-16f);
    float4 bias = *(const float4*)(b1 + c0);
    float ov[4];
    ov[0] = acc.x * w + bias.x;
    ov[1] = acc.y * w + bias.y;
    ov[2] = acc.z * w + bias.z;
    ov[3] = acc.w * w + bias.w;
#pragma unroll
    for (int j = 0; j < 4; j++)
        ov[j] = ov[j] > 0.f ? ov[j] : (__expf(ov[j]) - 1.f);   // ELU

    float pl0 = 0.f, pl1 = 0.f, pl2 = 0.f, pr0 = 0.f, pr1 = 0.f, pr2 = 0.f;
#pragma unroll
    for (int j = 0; j < 4; j++) {
        int k = c0 + j;
        pl0 += ov[j] * W2l[k * 3 + 0];
        pl1 += ov[j] * W2l[k * 3 + 1];
        pl2 += ov[j] * W2l[k * 3 + 2];
        pr0 += ov[j] * W2r[k * 3 + 0];
        pr1 += ov[j] * W2r[k * 3 + 1];
        pr2 += ov[j] * W2r[k * 3 + 2];
    }
#pragma unroll
    for (int s = 16; s; s >>= 1) {
        pl0 += __shfl_xor_sync(FULL, pl0, s);
        pl1 += __shfl_xor_sync(FULL, pl1, s);
        pl2 += __shfl_xor_sync(FULL, pl2, s);
        pr0 += __shfl_xor_sync(FULL, pr0, s);
        pr1 += __shfl_xor_sync(FULL, pr1, s);
        pr2 += __shfl_xor_sync(FULL, pr2, s);
    }
    if (lane == 0) {
        *(float4*)(g_xl2 + dst * 4) = make_float4(pl0, pl1, pl2, 0.f);
        *(float4*)(g_xr2 + dst * 4) = make_float4(pr0, pr1, pr2, 0.f);
    }
}

// ---------------- fused layer2 + pool + (last block) MLP --------------------
// 2 dsts per warp: lanes 0-15 -> dst0, lanes 16-31 -> dst1.
__global__ void fused_l2_mlp_kernel(const float* __restrict__ att2,
                                    const float* __restrict__ b2,
                                    const int* __restrict__ batch,
                                    const float* __restrict__ Wr1,
                                    const float* __restrict__ br1,
                                    const float* __restrict__ Wr2,
                                    const float* __restrict__ br2,
                                    float* __restrict__ out) {
    int warp_g = (blockIdx.x * blockDim.x + threadIdx.x) >> 5;
    int lane = threadIdx.x & 31;
    int sl = lane & 15;
    int dst = warp_g * 2 + (lane >> 4);

    if (dst < N_NODES) {
        float a0 = att2[0], a1 = att2[1], a2 = att2[2];
        float4 rv = *(const float4*)(g_xr2 + dst * 4);
        float d = 0.f, m0 = 0.f, m1 = 0.f, m2 = 0.f;
        int rs = g_rowptr[dst], re = g_rowptr[dst + 1];
        for (int i = rs + sl; i < re; i += 16) {
            int src = g_csr_src[i];
            float4 sv = *(const float4*)(g_xl2 + src * 4);
            float p = a0 * lrelu(sv.x + rv.x) + a1 * lrelu(sv.y + rv.y)
                    + a2 * lrelu(sv.z + rv.z);
            float ea = __expf(p);
            d += ea; m0 += ea * sv.x; m1 += ea * sv.y; m2 += ea * sv.z;
        }
#pragma unroll
        for (int o = 8; o; o >>= 1) {   // reduce within 16-lane group
            d  += __shfl_xor_sync(FULL, d, o);
            m0 += __shfl_xor_sync(FULL, m0, o);
            m1 += __shfl_xor_sync(FULL, m1, o);
            m2 += __shfl_xor_sync(FULL, m2, o);
        }
        if (sl == 0) {
            float w = __fdividef(1.f, d + 1e-16f);
            int g = batch[dst];
            atomicAdd(&g_pool[g * 4 + 0], m0 * w + b2[0]);
            atomicAdd(&g_pool[g * 4 + 1], m1 * w + b2[1]);
            atomicAdd(&g_pool[g * 4 + 2], m2 * w + b2[2]);
        }
    }

    // ---- last-block ticket: the final block to finish runs the MLP ----
    __syncthreads();
    __shared__ int s_last;
    if (threadIdx.x == 0) {
        __threadfence();
        int ticket = atomicAdd(&g_done, 1);
        s_last = (ticket == gridDim.x - 1) ? 1 : 0;
    }
    __syncthreads();
    if (!s_last) return;
    __threadfence();   // acquire: all pool atomics now visible

    int g = threadIdx.x;
    if (g < N_GRAPHS) {
        float cnt = g_pool[g * 4 + 3];
        float inv = 1.f / fmaxf(cnt, 1.f);
        float v0 = g_pool[g * 4 + 0] * inv;
        float v1 = g_pool[g * 4 + 1] * inv;
        float v2 = g_pool[g * 4 + 2] * inv;
        float o0 = br2[0], o1 = br2[1], o2 = br2[2];
#pragma unroll 8
        for (int j = 0; j < 64; j++) {
            float hj = v0 * Wr1[j] + v1 * Wr1[64 + j] + v2 * Wr1[128 + j] + br1[j];
            hj = fmaxf(hj, 0.f);
            o0 += hj * Wr2[j * 3 + 0];
            o1 += hj * Wr2[j * 3 + 1];
            o2 += hj * Wr2[j * 3 + 2];
        }
        out[g * 3 + 0] = o0;
        out[g * 3 + 1] = o1;
        out[g * 3 + 2] = o2;
    }
    __syncthreads();
    // restore invariants for next replay (pool read is complete)
    if (threadIdx.x < N_GRAPHS * 4) g_pool[threadIdx.x] = 0.f;
    if (threadIdx.x == 0) g_done = 0;
}

// ---------------- stream/event handles (created at static init) -------------
struct SideStream {
    cudaStream_t s;
    cudaEvent_t evFork, evJoin;
    SideStream() {
        cudaStreamCreateWithFlags(&s, cudaStreamNonBlocking);
        cudaEventCreateWithFlags(&evFork, cudaEventDisableTiming);
        cudaEventCreateWithFlags(&evJoin, cudaEventDisableTiming);
    }
};
static SideStream g_ss;

// ---------------- launch ----------------------------------------------------
extern "C" void kernel_launch(void* const* d_in, const int* in_sizes, int n_in,
                              void* d_out, int out_size) {
    (void)in_sizes; (void)n_in; (void)out_size;
    const float* x    = (const float*)d_in[0];
    const int*   ei   = (const int*)  d_in[1];
    const int*   batch= (const int*)  d_in[2];
    const float* W1l  = (const float*)d_in[3];
    const float* W1r  = (const float*)d_in[4];
    const float* att1 = (const float*)d_in[5];
    const float* b1   = (const float*)d_in[6];
    const float* W2l  = (const float*)d_in[7];
    const float* W2r  = (const float*)d_in[8];
    const float* att2 = (const float*)d_in[9];
    const float* b2   = (const float*)d_in[10];
    const float* Wr1  = (const float*)d_in[11];
    const float* br1  = (const float*)d_in[12];
    const float* Wr2  = (const float*)d_in[13];
    const float* br2  = (const float*)d_in[14];
    float* out = (float*)d_out;

    // fork: gemm1 runs concurrently with the CSR build
    cudaEventRecord(g_ss.evFork, 0);
    cudaStreamWaitEvent(g_ss.s, g_ss.evFork, 0);
    {
        dim3 grid((N_NODES + 127) / 128, 2);
        gemm1_kernel<<<grid, 256, 0, g_ss.s>>>(x, W1l, W1r);
    }
    cudaEventRecord(g_ss.evJoin, g_ss.s);

    csr_count_kernel<<<(ET + 255) / 256, 256>>>(ei, batch);
    scan_local_kernel<<<NB_SCAN, 256>>>();
    scan_apply_kernel<<<NB_SCAN, 256>>>();
    csr_fill_kernel<<<(ET + 255) / 256, 256>>>(ei);

    // join: fused_l1 needs both gemm1 output and CSR
    cudaStreamWaitEvent(0, g_ss.evJoin, 0);
    {
        long long t = (long long)N_NODES * 32;
        fused_l1_kernel<<<(unsigned)((t + 255) / 256), 256>>>(att1, b1, W2l, W2r);
    }
    fused_l2_mlp_kernel<<<L2_BLOCKS, 256>>>(att2, b2, batch,
                                            Wr1, br1, Wr2, br2, out);
}